// round 10
// baseline (speedup 1.0000x reference)
#include <cuda_runtime.h>
#include <cstdint>
#include <math.h>

// Problem constants
#define Bc   2
#define Sc   2048
#define Ec   1024
#define Hc   16
#define Dc   64
#define NTOK (Bc*Sc)          // 4096
#define ATT_SCALE 0.125f
#define KP2  (Ec/2)           // 512 pairs per row

// ---------------------------------------------------------------------------
// Scratch (static __device__ — no allocation allowed)
// packed bf16x2 pair buffers (hi, lo): [rows][K/2]
// ---------------------------------------------------------------------------
__device__ uint32_t g_xh [NTOK*KP2];
__device__ uint32_t g_xl [NTOK*KP2];
__device__ uint32_t g_qh [NTOK*KP2];
__device__ uint32_t g_ql [NTOK*KP2];
__device__ uint32_t g_kh [NTOK*KP2];
__device__ uint32_t g_kl [NTOK*KP2];
__device__ uint32_t g_vh [NTOK*KP2];
__device__ uint32_t g_vl [NTOK*KP2];
__device__ uint32_t g_ch [NTOK*KP2];
__device__ uint32_t g_cl [NTOK*KP2];
__device__ uint32_t g_wqh[Ec*KP2];
__device__ uint32_t g_wql[Ec*KP2];
__device__ uint32_t g_wkh[Ec*KP2];
__device__ uint32_t g_wkl[Ec*KP2];
__device__ uint32_t g_wvh[Ec*KP2];
__device__ uint32_t g_wvl[Ec*KP2];
__device__ uint32_t g_woh[Ec*KP2];
__device__ uint32_t g_wol[Ec*KP2];

// ---------------------------------------------------------------------------
// helpers
// ---------------------------------------------------------------------------
__device__ __forceinline__ void split_pack(float v0, float v1, uint32_t& h, uint32_t& l) {
    const uint32_t u0 = __float_as_uint(v0);
    const uint32_t u1 = __float_as_uint(v1);
    uint32_t hp;
    asm("prmt.b32 %0, %1, %2, 0x7632;" : "=r"(hp) : "r"(u0), "r"(u1));
    const float l0 = v0 - __uint_as_float(u0 & 0xFFFF0000u);
    const float l1 = v1 - __uint_as_float(u1 & 0xFFFF0000u);
    uint32_t lp;
    asm("cvt.rn.bf16x2.f32 %0, %1, %2;" : "=r"(lp) : "f"(l1), "f"(l0));
    h = hp; l = lp;
}

__device__ __forceinline__ void mma_bf16(float* c, const uint32_t* a, const uint32_t* b) {
    asm volatile(
        "mma.sync.aligned.m16n8k16.row.col.f32.bf16.bf16.f32 "
        "{%0,%1,%2,%3}, {%4,%5,%6,%7}, {%8,%9}, {%0,%1,%2,%3};"
        : "+f"(c[0]), "+f"(c[1]), "+f"(c[2]), "+f"(c[3])
        : "r"(a[0]), "r"(a[1]), "r"(a[2]), "r"(a[3]), "r"(b[0]), "r"(b[1]));
}

#define LDM4(r, addr) \
    asm volatile("ldmatrix.sync.aligned.m8n8.x4.shared.b16 {%0,%1,%2,%3}, [%4];" \
        : "=r"((r)[0]), "=r"((r)[1]), "=r"((r)[2]), "=r"((r)[3]) : "r"(addr))
#define LDM4T(r, addr) \
    asm volatile("ldmatrix.sync.aligned.m8n8.x4.trans.shared.b16 {%0,%1,%2,%3}, [%4];" \
        : "=r"((r)[0]), "=r"((r)[1]), "=r"((r)[2]), "=r"((r)[3]) : "r"(addr))
#define CPA16(dst, src) \
    asm volatile("cp.async.ca.shared.global [%0], [%1], 16;" :: "r"(dst), "l"(src))
#define CPA_COMMIT() asm volatile("cp.async.commit_group;" ::: "memory")

__device__ __forceinline__ uint32_t smem_u32(const void* p) {
    uint32_t a;
    asm("{ .reg .u64 t; cvta.to.shared.u64 t, %1; cvt.u32.u64 %0, t; }"
        : "=r"(a) : "l"(p));
    return a;
}

// ---------------------------------------------------------------------------
// split kernel: fp32 -> packed bf16x2 (hi, lo) pair arrays (x + weights only)
// ---------------------------------------------------------------------------
__global__ void __launch_bounds__(256) split_pairs(const float4* __restrict__ x,
                                                   uint2* __restrict__ hp,
                                                   uint2* __restrict__ lp, int n4) {
    const int i = blockIdx.x * 256 + threadIdx.x;
    if (i >= n4) return;
    float4 v = x[i];
    uint32_t h0, l0, h1, l1;
    split_pack(v.x, v.y, h0, l0);
    split_pack(v.z, v.w, h1, l1);
    hp[i] = make_uint2(h0, h1);
    lp[i] = make_uint2(l0, l1);
}

// ---------------------------------------------------------------------------
// 3xBF16 GEMM core: cp.async double-buffered + ldmatrix (unchanged from R9).
// ---------------------------------------------------------------------------
#define PRS  20
#define NPAN 32
#define ARRU (128*PRS)
#define ARRB (ARRU*4)
#define BUFU (4*ARRU)
#define BUFB (BUFU*4)
#define GEMM_SMEM (2*BUFB)     // 81920 B

template<bool PAIR>
__device__ __forceinline__ void gemm_core(const uint32_t* __restrict__ Ahg,
                                          const uint32_t* __restrict__ Alg,
                                          const uint32_t* __restrict__ Bhg,
                                          const uint32_t* __restrict__ Blg,
                                          uint32_t* __restrict__ Oh,
                                          uint32_t* __restrict__ Ol,
                                          float* __restrict__ Cf) {
    extern __shared__ uint32_t smu[];
    const uint32_t sb = smem_u32(smu);

    const int tid  = threadIdx.x;
    const int wid  = tid >> 5;
    const int lane = tid & 31;
    const int wm   = (wid & 1) * 64;
    const int wn   = (wid >> 1) * 32;
    const int m0   = blockIdx.y * 128;
    const int n0   = blockIdx.x * 128;
    const int lq   = lane >> 2;
    const int lr   = lane & 3;

    const uint32_t* gb[4] = { Ahg + (size_t)m0 * KP2, Alg + (size_t)m0 * KP2,
                              Bhg + (size_t)n0 * KP2, Blg + (size_t)n0 * KP2 };

    const uint32_t aPat = (uint32_t)((wm + (lane & 15)) * PRS + (lane >> 4) * 4) * 4;
    const uint32_t bPat = 2 * ARRB +
        (uint32_t)((wn + (lane & 7) + ((lane >> 4) & 1) * 8) * PRS + ((lane >> 3) & 1) * 4) * 4;

    float acc[4][4][4];
    #pragma unroll
    for (int i = 0; i < 4; i++)
        #pragma unroll
        for (int j = 0; j < 4; j++)
            #pragma unroll
            for (int e = 0; e < 4; e++) acc[i][j][e] = 0.f;

    #define STAGE(p, buf) do {                                                  \
        const int _pb = (p) * 16;                                               \
        _Pragma("unroll")                                                       \
        for (int arr = 0; arr < 4; arr++) {                                     \
            _Pragma("unroll")                                                   \
            for (int j = 0; j < 2; j++) {                                       \
                const int i   = tid + j * 256;                                  \
                const int row = i >> 2;                                         \
                const int c   = (i & 3) * 4;                                    \
                const uint32_t* src = gb[arr] + (size_t)row * KP2 + _pb + c;    \
                const uint32_t dst = sb +                                       \
                    (uint32_t)((buf) * BUFU + arr * ARRU + row * PRS + c) * 4;  \
                CPA16(dst, src);                                                \
            }                                                                   \
        }                                                                       \
        CPA_COMMIT();                                                           \
    } while (0)

    STAGE(0, 0);

    for (int p = 0; p < NPAN; p++) {
        if (p + 1 < NPAN) {
            STAGE(p + 1, (p + 1) & 1);
            asm volatile("cp.async.wait_group 1;" ::: "memory");
        } else {
            asm volatile("cp.async.wait_group 0;" ::: "memory");
        }
        __syncthreads();

        const uint32_t bufB = (uint32_t)(p & 1) * BUFB;

        #pragma unroll
        for (int s2 = 0; s2 < 2; s2++) {
            const uint32_t pbB = (uint32_t)s2 * 32;
            uint32_t ah[4][4], al[4][4];
            const uint32_t aa = sb + bufB + aPat + pbB;
            #pragma unroll
            for (int mt = 0; mt < 4; mt++) {
                LDM4(ah[mt], aa + (uint32_t)(mt * 16 * PRS) * 4);
                LDM4(al[mt], aa + (uint32_t)(mt * 16 * PRS) * 4 + ARRB);
            }
            const uint32_t ba = sb + bufB + bPat + pbB;
            #pragma unroll
            for (int ntp = 0; ntp < 2; ntp++) {
                uint32_t bh[4], bl[4];
                LDM4(bh, ba + (uint32_t)(ntp * 16 * PRS) * 4);
                LDM4(bl, ba + (uint32_t)(ntp * 16 * PRS) * 4 + ARRB);
                #pragma unroll
                for (int mt = 0; mt < 4; mt++) {
                    mma_bf16(acc[mt][2*ntp],   ah[mt], bh);
                    mma_bf16(acc[mt][2*ntp],   ah[mt], bl);
                    mma_bf16(acc[mt][2*ntp],   al[mt], bh);
                    mma_bf16(acc[mt][2*ntp+1], ah[mt], bh + 2);
                    mma_bf16(acc[mt][2*ntp+1], ah[mt], bl + 2);
                    mma_bf16(acc[mt][2*ntp+1], al[mt], bh + 2);
                }
            }
        }
        __syncthreads();
    }

    #pragma unroll
    for (int mt = 0; mt < 4; mt++) {
        const int r0 = m0 + wm + mt * 16 + lq;
        #pragma unroll
        for (int nt = 0; nt < 4; nt++) {
            if (PAIR) {
                const int pidx = ((n0 + wn + nt * 8) >> 1) + lr;
                uint32_t h, l;
                split_pack(acc[mt][nt][0], acc[mt][nt][1], h, l);
                Oh[(size_t)r0 * KP2 + pidx] = h;
                Ol[(size_t)r0 * KP2 + pidx] = l;
                split_pack(acc[mt][nt][2], acc[mt][nt][3], h, l);
                Oh[(size_t)(r0 + 8) * KP2 + pidx] = h;
                Ol[(size_t)(r0 + 8) * KP2 + pidx] = l;
            } else {
                const int cc = n0 + wn + nt * 8 + lr * 2;
                *(float2*)&Cf[(size_t)r0 * Ec + cc]       = make_float2(acc[mt][nt][0], acc[mt][nt][1]);
                *(float2*)&Cf[(size_t)(r0 + 8) * Ec + cc] = make_float2(acc[mt][nt][2], acc[mt][nt][3]);
            }
        }
    }
}

__global__ void __launch_bounds__(256, 2) gemm_qkv(
    const uint32_t* __restrict__ xh,  const uint32_t* __restrict__ xl,
    const uint32_t* __restrict__ wqh, const uint32_t* __restrict__ wql,
    const uint32_t* __restrict__ wkh, const uint32_t* __restrict__ wkl,
    const uint32_t* __restrict__ wvh, const uint32_t* __restrict__ wvl,
    uint32_t* __restrict__ qh, uint32_t* __restrict__ ql,
    uint32_t* __restrict__ kh, uint32_t* __restrict__ kl,
    uint32_t* __restrict__ vh, uint32_t* __restrict__ vl) {
    const uint32_t *bh, *bl;
    uint32_t *oh, *ol;
    if (blockIdx.z == 0)      { bh = wqh; bl = wql; oh = qh; ol = ql; }
    else if (blockIdx.z == 1) { bh = wkh; bl = wkl; oh = kh; ol = kl; }
    else                      { bh = wvh; bl = wvl; oh = vh; ol = vl; }
    gemm_core<true>(xh, xl, bh, bl, oh, ol, nullptr);
}

__global__ void __launch_bounds__(256, 2) gemm_wo(
    const uint32_t* __restrict__ ch, const uint32_t* __restrict__ cl,
    const uint32_t* __restrict__ woh, const uint32_t* __restrict__ wol,
    float* __restrict__ out) {
    gemm_core<false>(ch, cl, woh, wol, nullptr, nullptr, out);
}

// ---------------------------------------------------------------------------
// Flash attention, causal, 3xBF16. Br=128, 4 warps (warp = 32 rows x 64 keys),
// K/V double-buffered via cp.async groups. 110592 B smem -> 2 CTAs/SM.
// ---------------------------------------------------------------------------
#define PST   36
#define QARR  (128*PST)                  // u32 per Q array
#define QLBq  ((uint32_t)QARR*4)         // bytes between Qh and Ql
#define KVOFF (2*QLBq)                   // byte offset of KV buffer 0
#define KVB   ((uint32_t)(64*PST)*4)     // bytes per KV array
#define BUFOFF (4*KVB)                   // bytes per KV buffer
#define FA_SMEM (KVOFF + 2*BUFOFF)       // 110592 B

__global__ void __launch_bounds__(128, 2) flash_attn_mma(
    const uint32_t* __restrict__ Qh, const uint32_t* __restrict__ Ql,
    const uint32_t* __restrict__ Kh, const uint32_t* __restrict__ Kl,
    const uint32_t* __restrict__ Vh, const uint32_t* __restrict__ Vl,
    uint32_t* __restrict__ Ch, uint32_t* __restrict__ Cl) {
    extern __shared__ uint32_t smu[];
    const uint32_t sbq = smem_u32(smu);

    const int tid  = threadIdx.x;
    const int wid  = tid >> 5;
    const int lane = tid & 31;
    const int lq   = lane >> 2;
    const int lr   = lane & 3;
    const int wrow = wid * 32;

    const int qt = gridDim.x - 1 - blockIdx.x;   // long CTAs first
    const int h  = blockIdx.y;
    const int b  = blockIdx.z;
    const int hb = h * 32;
    const size_t rb = (size_t)b * Sc;
    const int rowbase = qt * 128;
    const int jtmax = 2 * qt + 1;

    // fragment lane patterns (byte offsets)
    const uint32_t aPat = sbq +
        (uint32_t)((wrow + (lane & 15)) * PST + (lane >> 4) * 4) * 4;
    const uint32_t kPat =
        (uint32_t)(((lane & 7) + ((lane >> 4) & 1) * 8) * PST + ((lane >> 3) & 1) * 4) * 4;
    const uint32_t vPat = 2 * KVB +
        (uint32_t)(((lane & 7) + ((lane >> 3) & 1) * 8) * PST + ((lane >> 4) & 1) * 4) * 4;

    // stage Q (group 0, together with KV tile 0)
    #pragma unroll
    for (int it = 0; it < 8; it++) {
        const int i   = tid + it * 128;          // 1024 chunks per array
        const int row = i >> 3;
        const int c   = (i & 7) * 4;
        const size_t src = (rb + rowbase + row) * KP2 + hb + c;
        const uint32_t dst = sbq + (uint32_t)(row * PST + c) * 4;
        CPA16(dst, Qh + src);
        CPA16(dst + QLBq, Ql + src);
    }
    // stage KV tile 0 into buffer 0
    #pragma unroll
    for (int it = 0; it < 4; it++) {
        const int i   = tid + it * 128;
        const int row = i >> 3;
        const int c   = (i & 7) * 4;
        const size_t src = (rb + row) * KP2 + hb + c;
        const uint32_t dst = sbq + KVOFF + (uint32_t)(row * PST + c) * 4;
        CPA16(dst,           Kh + src);
        CPA16(dst + KVB,     Kl + src);
        CPA16(dst + 2 * KVB, Vh + src);
        CPA16(dst + 3 * KVB, Vl + src);
    }
    CPA_COMMIT();

    float o[2][8][4];
    #pragma unroll
    for (int hh = 0; hh < 2; hh++)
        #pragma unroll
        for (int nt = 0; nt < 8; nt++)
            #pragma unroll
            for (int e = 0; e < 4; e++) o[hh][nt][e] = 0.f;
    float mrow[2][2] = {{-1e30f, -1e30f}, {-1e30f, -1e30f}};
    float lrow[2][2] = {{0.f, 0.f}, {0.f, 0.f}};

    const unsigned FM = 0xffffffffu;

    for (int jt = 0; jt <= jtmax; jt++) {
        __syncthreads();   // all warps done reading buf[(jt+1)&1] (iter jt-1)
        if (jt < jtmax) {
            const uint32_t kvb = sbq + KVOFF + (uint32_t)((jt + 1) & 1) * BUFOFF;
            #pragma unroll
            for (int it = 0; it < 4; it++) {
                const int i   = tid + it * 128;
                const int row = i >> 3;
                const int c   = (i & 7) * 4;
                const size_t src = (rb + (jt + 1) * 64 + row) * KP2 + hb + c;
                const uint32_t dst = kvb + (uint32_t)(row * PST + c) * 4;
                CPA16(dst,           Kh + src);
                CPA16(dst + KVB,     Kl + src);
                CPA16(dst + 2 * KVB, Vh + src);
                CPA16(dst + 3 * KVB, Vl + src);
            }
            CPA_COMMIT();
            asm volatile("cp.async.wait_group 1;" ::: "memory");
        } else {
            asm volatile("cp.async.wait_group 0;" ::: "memory");
        }
        __syncthreads();

        if (jt * 64 > rowbase + wrow + 31) continue;   // warp causal skip

        const uint32_t kvb = sbq + KVOFF + (uint32_t)(jt & 1) * BUFOFF;
        const uint32_t kBase = kvb + kPat;
        const uint32_t vBase = kvb + vPat;

        // S = Q @ K^T
        float s[2][8][4];
        #pragma unroll
        for (int hh = 0; hh < 2; hh++)
            #pragma unroll
            for (int nt = 0; nt < 8; nt++)
                #pragma unroll
                for (int e = 0; e < 4; e++) s[hh][nt][e] = 0.f;

        #pragma unroll
        for (int ks = 0; ks < 4; ks++) {
            const uint32_t pbB = (uint32_t)ks * 32;
            uint32_t ah[2][4], al[2][4];
            #pragma unroll
            for (int hh = 0; hh < 2; hh++) {
                const uint32_t aa = aPat + (uint32_t)(hh * 16 * PST) * 4 + pbB;
                LDM4(ah[hh], aa);
                LDM4(al[hh], aa + QLBq);
            }
            #pragma unroll
            for (int ntp = 0; ntp < 4; ntp++) {
                const uint32_t ka = kBase + (uint32_t)(ntp * 16 * PST) * 4 + pbB;
                uint32_t bh[4], bl[4];
                LDM4(bh, ka);
                LDM4(bl, ka + KVB);
                #pragma unroll
                for (int hh = 0; hh < 2; hh++) {
                    mma_bf16(s[hh][2*ntp],   ah[hh], bh);
                    mma_bf16(s[hh][2*ntp],   ah[hh], bl);
                    mma_bf16(s[hh][2*ntp],   al[hh], bh);
                    mma_bf16(s[hh][2*ntp+1], ah[hh], bh + 2);
                    mma_bf16(s[hh][2*ntp+1], ah[hh], bl + 2);
                    mma_bf16(s[hh][2*ntp+1], al[hh], bh + 2);
                }
            }
        }

        // scale + causal mask
        if (jt * 64 + 63 > rowbase + wrow) {
            #pragma unroll
            for (int hh = 0; hh < 2; hh++) {
                const int row0 = rowbase + wrow + hh * 16 + lq;
                const int row1 = row0 + 8;
                #pragma unroll
                for (int nt = 0; nt < 8; nt++) {
                    const int c0 = jt * 64 + nt * 8 + lr * 2;
                    s[hh][nt][0] = (c0     > row0) ? -1e30f : s[hh][nt][0] * ATT_SCALE;
                    s[hh][nt][1] = (c0 + 1 > row0) ? -1e30f : s[hh][nt][1] * ATT_SCALE;
                    s[hh][nt][2] = (c0     > row1) ? -1e30f : s[hh][nt][2] * ATT_SCALE;
                    s[hh][nt][3] = (c0 + 1 > row1) ? -1e30f : s[hh][nt][3] * ATT_SCALE;
                }
            }
        } else {
            #pragma unroll
            for (int hh = 0; hh < 2; hh++)
                #pragma unroll
                for (int nt = 0; nt < 8; nt++)
                    #pragma unroll
                    for (int e = 0; e < 4; e++) s[hh][nt][e] *= ATT_SCALE;
        }

        // online softmax (per row-half)
        #pragma unroll
        for (int hh = 0; hh < 2; hh++) {
            float mt0 = -1e30f, mt1 = -1e30f;
            #pragma unroll
            for (int nt = 0; nt < 8; nt++) {
                mt0 = fmaxf(mt0, fmaxf(s[hh][nt][0], s[hh][nt][1]));
                mt1 = fmaxf(mt1, fmaxf(s[hh][nt][2], s[hh][nt][3]));
            }
            mt0 = fmaxf(mt0, __shfl_xor_sync(FM, mt0, 1));
            mt0 = fmaxf(mt0, __shfl_xor_sync(FM, mt0, 2));
            mt1 = fmaxf(mt1, __shfl_xor_sync(FM, mt1, 1));
            mt1 = fmaxf(mt1, __shfl_xor_sync(FM, mt1, 2));
            const float mn0 = fmaxf(mrow[hh][0], mt0);
            const float mn1 = fmaxf(mrow[hh][1], mt1);
            const float a0 = __expf(mrow[hh][0] - mn0);
            const float a1 = __expf(mrow[hh][1] - mn1);
            float rs0 = 0.f, rs1 = 0.f;
            #pragma unroll
            for (int nt = 0; nt < 8; nt++) {
                s[hh][nt][0] = __expf(s[hh][nt][0] - mn0); rs0 += s[hh][nt][0];
                s[hh][nt][1] = __expf(s[hh][nt][1] - mn0); rs0 += s[hh][nt][1];
                s[hh][nt][2] = __expf(s[hh][nt][2] - mn1); rs1 += s[hh][nt][2];
                s[hh][nt][3] = __expf(s[hh][nt][3] - mn1); rs1 += s[hh][nt][3];
            }
            rs0 += __shfl_xor_sync(FM, rs0, 1);
            rs0 += __shfl_xor_sync(FM, rs0, 2);
            rs1 += __shfl_xor_sync(FM, rs1, 1);
            rs1 += __shfl_xor_sync(FM, rs1, 2);
            lrow[hh][0] = lrow[hh][0] * a0 + rs0; mrow[hh][0] = mn0;
            lrow[hh][1] = lrow[hh][1] * a1 + rs1; mrow[hh][1] = mn1;
            #pragma unroll
            for (int nt = 0; nt < 8; nt++) {
                o[hh][nt][0] *= a0; o[hh][nt][1] *= a0;
                o[hh][nt][2] *= a1; o[hh][nt][3] *= a1;
            }
        }

        // O += P @ V (P from S registers, V via ldmatrix.trans)
        #pragma unroll
        for (int ks = 0; ks < 4; ks++) {
            uint32_t ph[2][4], pl[2][4];
            #pragma unroll
            for (int hh = 0; hh < 2; hh++) {
                split_pack(s[hh][2*ks][0],   s[hh][2*ks][1],   ph[hh][0], pl[hh][0]);
                split_pack(s[hh][2*ks][2],   s[hh][2*ks][3],   ph[hh][1], pl[hh][1]);
                split_pack(s[hh][2*ks+1][0], s[hh][2*ks+1][1], ph[hh][2], pl[hh][2]);
                split_pack(s[hh][2*ks+1][2], s[hh][2*ks+1][3], ph[hh][3], pl[hh][3]);
            }
            const uint32_t kOfs = (uint32_t)(ks * 16 * PST) * 4;
            #pragma unroll
            for (int ntp = 0; ntp < 4; ntp++) {
                const uint32_t va = vBase + kOfs + (uint32_t)(ntp * 8) * 4;
                uint32_t vh[4], vl[4];
                LDM4T(vh, va);
                LDM4T(vl, va + KVB);
                #pragma unroll
                for (int hh = 0; hh < 2; hh++) {
                    mma_bf16(o[hh][2*ntp],   ph[hh], vh);
                    mma_bf16(o[hh][2*ntp],   ph[hh], vl);
                    mma_bf16(o[hh][2*ntp],   pl[hh], vh);
                    mma_bf16(o[hh][2*ntp+1], ph[hh], vh + 2);
                    mma_bf16(o[hh][2*ntp+1], ph[hh], vl + 2);
                    mma_bf16(o[hh][2*ntp+1], pl[hh], vh + 2);
                }
            }
        }
    }

    // epilogue: normalize, write split pairs for the WO GEMM
    #pragma unroll
    for (int hh = 0; hh < 2; hh++) {
        const float inv0 = 1.0f / lrow[hh][0];
        const float inv1 = 1.0f / lrow[hh][1];
        const size_t ro0 = (rb + rowbase + wrow + hh * 16 + lq) * KP2 + hb;
        const size_t ro1 = ro0 + 8 * (size_t)KP2;
        #pragma unroll
        for (int nt = 0; nt < 8; nt++) {
            const int pidx = nt * 4 + lr;
            uint32_t hp, lp;
            split_pack(o[hh][nt][0] * inv0, o[hh][nt][1] * inv0, hp, lp);
            Ch[ro0 + pidx] = hp; Cl[ro0 + pidx] = lp;
            split_pack(o[hh][nt][2] * inv1, o[hh][nt][3] * inv1, hp, lp);
            Ch[ro1 + pidx] = hp; Cl[ro1 + pidx] = lp;
        }
    }
}

// ---------------------------------------------------------------------------
extern "C" void kernel_launch(void* const* d_in, const int* in_sizes, int n_in,
                              void* d_out, int out_size) {
    (void)in_sizes; (void)n_in; (void)out_size;
    const float* x  = (const float*)d_in[0];
    const float* wq = (const float*)d_in[1];
    const float* wk = (const float*)d_in[2];
    const float* wv = (const float*)d_in[3];
    const float* wo = (const float*)d_in[4];
    float* out = (float*)d_out;

    uint32_t *xh, *xl, *qh, *ql, *kh, *kl, *vh, *vl, *ch, *cl;
    uint32_t *wqh, *wql, *wkh, *wkl, *wvh, *wvl, *woh, *wol;
    cudaGetSymbolAddress((void**)&xh,  g_xh);
    cudaGetSymbolAddress((void**)&xl,  g_xl);
    cudaGetSymbolAddress((void**)&qh,  g_qh);
    cudaGetSymbolAddress((void**)&ql,  g_ql);
    cudaGetSymbolAddress((void**)&kh,  g_kh);
    cudaGetSymbolAddress((void**)&kl,  g_kl);
    cudaGetSymbolAddress((void**)&vh,  g_vh);
    cudaGetSymbolAddress((void**)&vl,  g_vl);
    cudaGetSymbolAddress((void**)&ch,  g_ch);
    cudaGetSymbolAddress((void**)&cl,  g_cl);
    cudaGetSymbolAddress((void**)&wqh, g_wqh);
    cudaGetSymbolAddress((void**)&wql, g_wql);
    cudaGetSymbolAddress((void**)&wkh, g_wkh);
    cudaGetSymbolAddress((void**)&wkl, g_wkl);
    cudaGetSymbolAddress((void**)&wvh, g_wvh);
    cudaGetSymbolAddress((void**)&wvl, g_wvl);
    cudaGetSymbolAddress((void**)&woh, g_woh);
    cudaGetSymbolAddress((void**)&wol, g_wol);

    const int nx4 = NTOK * Ec / 4;
    const int nw4 = Ec * Ec / 4;
    split_pairs<<<nx4 / 256, 256>>>((const float4*)x,  (uint2*)xh,  (uint2*)xl,  nx4);
    split_pairs<<<nw4 / 256, 256>>>((const float4*)wq, (uint2*)wqh, (uint2*)wql, nw4);
    split_pairs<<<nw4 / 256, 256>>>((const float4*)wk, (uint2*)wkh, (uint2*)wkl, nw4);
    split_pairs<<<nw4 / 256, 256>>>((const float4*)wv, (uint2*)wvh, (uint2*)wvl, nw4);
    split_pairs<<<nw4 / 256, 256>>>((const float4*)wo, (uint2*)woh, (uint2*)wol, nw4);

    cudaFuncSetAttribute(gemm_qkv, cudaFuncAttributeMaxDynamicSharedMemorySize, GEMM_SMEM);
    cudaFuncSetAttribute(gemm_wo,  cudaFuncAttributeMaxDynamicSharedMemorySize, GEMM_SMEM);

    gemm_qkv<<<dim3(Ec / 128, NTOK / 128, 3), 256, GEMM_SMEM>>>(
        xh, xl, wqh, wql, wkh, wkl, wvh, wvl, qh, ql, kh, kl, vh, vl);

    cudaFuncSetAttribute(flash_attn_mma, cudaFuncAttributeMaxDynamicSharedMemorySize, FA_SMEM);
    flash_attn_mma<<<dim3(Sc / 128, Hc, Bc), 128, FA_SMEM>>>(qh, ql, kh, kl, vh, vl, ch, cl);

    gemm_wo<<<dim3(Ec / 128, NTOK / 128), 256, GEMM_SMEM>>>(ch, cl, woh, wol, out);
}